// round 14
// baseline (speedup 1.0000x reference)
#include <cuda_runtime.h>
#include <cuda_fp16.h>
#include <math.h>
#include <stdint.h>

// Problem constants
#define BB   8
#define SS   2048
#define HH   16
#define DHH  64
#define DD   1024            // H*DH
#define MM   (BB*SS)         // 16384

#define WSCALE     256.0f
#define WSCALE_INV 0.00390625f

// ---------------- scratch (__device__ globals; allocation-free) -------------
__device__ __half g_Qh   [MM*DD];        // Q = Q_seq @ WQ  (fp16)
__device__ __half g_Kh   [MM*DD];        // K = K_seq @ WK  (fp16)
__device__ float g_logits[BB*HH*SS];     // (B,H,S)
__device__ float g_gq    [BB*HH*DHH];
__device__ float g_gk    [BB*HH*DHH];
__device__ float g_Wt    [2*HH*DD];      // transposed Wq (slot0) / Wk (slot1)
__device__ __half g_Af16[2*MM*DD];       // fp16 A (2 slots for merged GEMM1/2)
__device__ __half g_Bf16[2*DD*DD];       // transposed weights Bt[n,k], x256, fp16
__device__ __half g_BP  [BB*DD*DD];      // per-batch gk-scaled WPt[n,k], x256, fp16

// ======================= PTX helpers ========================================
__device__ __forceinline__ uint32_t smem_to_u32(const void* p) {
    uint32_t a;
    asm("{ .reg .u64 t; cvta.to.shared.u64 t, %1; cvt.u32.u64 %0, t; }"
        : "=r"(a) : "l"(p));
    return a;
}
#define LDSM4(r, addr) asm volatile( \
    "ldmatrix.sync.aligned.m8n8.x4.shared.b16 {%0,%1,%2,%3}, [%4];" \
    : "=r"((r)[0]), "=r"((r)[1]), "=r"((r)[2]), "=r"((r)[3]) : "r"(addr))
#define MMA_F16(d, a, b) asm volatile( \
    "mma.sync.aligned.m16n8k16.row.col.f32.f16.f16.f32 " \
    "{%0,%1,%2,%3}, {%4,%5,%6,%7}, {%8,%9}, {%0,%1,%2,%3};" \
    : "+f"((d)[0]), "+f"((d)[1]), "+f"((d)[2]), "+f"((d)[3]) \
    : "r"((a)[0]), "r"((a)[1]), "r"((a)[2]), "r"((a)[3]), \
      "r"((b)[0]), "r"((b)[1]))
__device__ __forceinline__ void cp16(uint32_t dst, const void* src) {
    asm volatile("cp.async.cg.shared.global [%0], [%1], 16;"
                 :: "r"(dst), "l"(src) : "memory");
}
#define CP_COMMIT()  asm volatile("cp.async.commit_group;" ::: "memory")
#define CP_WAIT_1()  asm volatile("cp.async.wait_group 1;" ::: "memory")
#define CP_WAIT_0()  asm volatile("cp.async.wait_group 0;" ::: "memory")

__device__ __forceinline__ uint32_t pack_h(float a, float b) {
    __half2 t;
    t.x = __float2half_rn(a);
    t.y = __float2half_rn(b);
    return *(uint32_t*)&t;
}

// ======================= HMMA fp16 GEMM =====================================
// acc = (1/256) * Af16 @ Bf16, B pre-scaled x256.
// RES=false: write __half to H0/H1 (by z), B indexed by z.
// RES=true:  write float to F with fp16 residual; B indexed per batch
//            (b = blockIdx.y>>4) — used for the gk-scaled WP copies.
#define NST       3
#define STAGE_B   32768
#define GEMM_SMEM (NST * STAGE_B)     // 98304
#define KB2       16                  // 1024 / 64

template<bool RES>
__global__ __launch_bounds__(256, 2) void hmma_gemm_kernel(
    const __half* __restrict__ A, const __half* __restrict__ B,
    __half* __restrict__ H0, __half* __restrict__ H1,
    float* __restrict__ F, const __half* __restrict__ res)
{
    extern __shared__ __align__(128) char smem[];
    const uint32_t sb = smem_to_u32(smem);
    const int tid = threadIdx.x;
    const int lane = tid & 31;
    const int wid  = tid >> 5;
    const int warpM = wid >> 2;            // 0..1
    const int warpN = wid & 3;             // 0..3
    const int colBase = blockIdx.x * 128;
    const int rowBase = blockIdx.y * 128;
    const int z = blockIdx.z;
    const size_t aZ = (size_t)z * MM * DD;
    const size_t bZ = RES ? (size_t)(blockIdx.y >> 4) * DD * DD
                          : (size_t)z * DD * DD;

    // ---- cp.async mapping: row = tid>>1, 4 x 16B chunks per half-row per buf
    const int crow = tid >> 1;                      // 0..127
    const int half = tid & 1;
    const int rsw  = crow & 7;
    uint32_t dOff[4];
    #pragma unroll
    for (int i = 0; i < 4; i++)
        dOff[i] = crow * 128 + (((half * 4 + i) ^ rsw) << 4);
    const char* pA = (const char*)(A + aZ + (size_t)(rowBase + crow) * DD) + half * 64;
    const char* pB = (const char*)(B + bZ + (size_t)(colBase + crow) * DD) + half * 64;

    #define ISSUE(s, kb) do {                                              \
        const uint32_t bs_ = sb + (s) * STAGE_B;                           \
        const int ko_ = (kb) * 128;                                        \
        _Pragma("unroll")                                                  \
        for (int i = 0; i < 4; i++) {                                      \
            cp16(bs_ + dOff[i],         pA + ko_ + i * 16);                \
            cp16(bs_ + 16384 + dOff[i], pB + ko_ + i * 16);                \
        }                                                                  \
        CP_COMMIT();                                                       \
    } while (0)

    // ---- ldmatrix row bases + swizzle keys
    const int lrow = lane & 15;
    const int hi16 = lane >> 4;
    uint32_t aRow[4]; int aSw[4];
    #pragma unroll
    for (int mf = 0; mf < 4; mf++) {
        const int r = warpM * 64 + mf * 16 + lrow;
        aRow[mf] = r * 128; aSw[mf] = r & 7;
    }
    uint32_t bRow[2]; int bSw[2];
    #pragma unroll
    for (int np = 0; np < 2; np++) {
        const int r = warpN * 32 + np * 16 + lrow;
        bRow[np] = r * 128; bSw[np] = r & 7;
    }

    ISSUE(0, 0);
    ISSUE(1, 1);

    float acc[4][4][4];
    #pragma unroll
    for (int mf = 0; mf < 4; mf++)
        #pragma unroll
        for (int nf = 0; nf < 4; nf++)
            #pragma unroll
            for (int q = 0; q < 4; q++) acc[mf][nf][q] = 0.f;

    for (int kb = 0; kb < KB2; kb++) {
        if (kb == KB2 - 1) { CP_WAIT_0(); } else { CP_WAIT_1(); }
        __syncthreads();
        if (kb + 2 < KB2) ISSUE((kb + 2) % NST, kb + 2);

        const uint32_t st = sb + (kb % NST) * STAGE_B;
        #pragma unroll
        for (int ks = 0; ks < 4; ks++) {
            const int ck = ks * 2 + hi16;
            uint32_t b0[4][2];
            #pragma unroll
            for (int np = 0; np < 2; np++) {
                uint32_t r[4];
                LDSM4(r, st + 16384 + bRow[np] + (((ck ^ bSw[np])) << 4));
                b0[np * 2 + 0][0] = r[0]; b0[np * 2 + 0][1] = r[2];
                b0[np * 2 + 1][0] = r[1]; b0[np * 2 + 1][1] = r[3];
            }
            uint32_t a[4][4];
            #pragma unroll
            for (int mf = 0; mf < 4; mf++)
                LDSM4(a[mf], st + aRow[mf] + (((ck ^ aSw[mf])) << 4));
            #pragma unroll
            for (int mf = 0; mf < 4; mf++)
                #pragma unroll
                for (int nf = 0; nf < 4; nf++)
                    MMA_F16(acc[mf][nf], a[mf], b0[nf]);
        }
    }
    #undef ISSUE

    // ---- epilogue (undo x256 weight scale)
    const int er = lane >> 2;
    const int ec = (lane & 3) * 2;
    __half* Hout = z ? H1 : H0;
    #pragma unroll
    for (int mf = 0; mf < 4; mf++) {
        const int row0 = rowBase + warpM * 64 + mf * 16 + er;
        #pragma unroll
        for (int nf = 0; nf < 4; nf++) {
            const int col = colBase + warpN * 32 + nf * 8 + ec;
            const float a0 = acc[mf][nf][0] * WSCALE_INV;
            const float a1 = acc[mf][nf][1] * WSCALE_INV;
            const float a2 = acc[mf][nf][2] * WSCALE_INV;
            const float a3 = acc[mf][nf][3] * WSCALE_INV;
            if (RES) {
                const __half2 r0 = *(const __half2*)(res + (size_t)row0 * DD + col);
                const __half2 r1 = *(const __half2*)(res + (size_t)(row0 + 8) * DD + col);
                float2 v0 = make_float2(a0 + __half2float(r0.x), a1 + __half2float(r0.y));
                float2 v1 = make_float2(a2 + __half2float(r1.x), a3 + __half2float(r1.y));
                *(float2*)(F + (size_t)row0 * DD + col) = v0;
                *(float2*)(F + (size_t)(row0 + 8) * DD + col) = v1;
            } else {
                *(uint32_t*)(Hout + (size_t)row0 * DD + col) = pack_h(a0, a1);
                *(uint32_t*)(Hout + (size_t)(row0 + 8) * DD + col) = pack_h(a2, a3);
            }
        }
    }
}

// ======================= A conversion (fp32 -> fp16) ========================
__global__ __launch_bounds__(256) void tohalf_kernel(
    const float* __restrict__ in0, const float* __restrict__ in1,
    __half* __restrict__ o)
{
    const size_t e = ((size_t)blockIdx.x * 256 + threadIdx.x) * 8;
    const float* in = blockIdx.y ? in1 : in0;
    const size_t oz = (size_t)blockIdx.y * ((size_t)MM * DD);
    float4 v0 = *(const float4*)(in + e);
    float4 v1 = *(const float4*)(in + e + 4);
    uint4 h = make_uint4(pack_h(v0.x, v0.y), pack_h(v0.z, v0.w),
                         pack_h(v1.x, v1.y), pack_h(v1.z, v1.w));
    *(uint4*)(o + oz + e) = h;
}

// ======================= weight transpose (x256, fp16) ======================
__global__ __launch_bounds__(256) void wsplit_kernel(
    const float* __restrict__ W0, const float* __restrict__ W1,
    __half* __restrict__ bh)
{
    __shared__ float tile[32][33];
    const float* W = blockIdx.z ? W1 : W0;
    const size_t oz = (size_t)blockIdx.z * DD * DD;
    const int tx = threadIdx.x & 31, ty0 = threadIdx.x >> 5;
    const int nbase = blockIdx.x * 32, kbase = blockIdx.y * 32;
    #pragma unroll
    for (int j = 0; j < 4; j++) {
        int r = ty0 + j * 8;
        tile[r][tx] = W[(size_t)(kbase + r) * DD + nbase + tx];
    }
    __syncthreads();
    #pragma unroll
    for (int j = 0; j < 4; j++) {
        int n = nbase + ty0 + j * 8;
        int k = kbase + tx;
        bh[oz + (size_t)n * DD + k] = __float2half_rn(tile[tx][ty0 + j * 8] * WSCALE);
    }
}

// ======= per-batch gk-scaled WP transpose: BP[b][n][k] = WP[k][n]*gk[b,k]*256
__global__ __launch_bounds__(256) void wpscale_kernel(
    const float* __restrict__ WP, const float* __restrict__ gk,
    __half* __restrict__ bp)
{
    __shared__ float tile[32][33];
    const int b = blockIdx.z;
    const size_t oz = (size_t)b * DD * DD;
    const int tx = threadIdx.x & 31, ty0 = threadIdx.x >> 5;
    const int nbase = blockIdx.x * 32, kbase = blockIdx.y * 32;
    #pragma unroll
    for (int j = 0; j < 4; j++) {
        int r = ty0 + j * 8;
        tile[r][tx] = WP[(size_t)(kbase + r) * DD + nbase + tx];
    }
    __syncthreads();
    const float gv = gk[b * DD + kbase + tx] * WSCALE;
    #pragma unroll
    for (int j = 0; j < 4; j++) {
        int n = nbase + ty0 + j * 8;
        int k = kbase + tx;
        bp[oz + (size_t)n * DD + k] = __float2half_rn(tile[tx][ty0 + j * 8] * gv);
    }
}

// ======================= small-W transpose (Wq/Wk -> Wt[h][d]) ==============
__global__ __launch_bounds__(256) void wtrans_kernel(
    const float* __restrict__ W0, const float* __restrict__ W1,
    float* __restrict__ Wt)
{
    const int idx = blockIdx.x * 256 + threadIdx.x;      // 0..16383
    const float* W = blockIdx.y ? W1 : W0;
    const int h = idx >> 10, d = idx & (DD - 1);
    Wt[blockIdx.y * (HH * DD) + idx] = W[d * HH + h];
}

// ======================= middle kernels =====================================
__global__ __launch_bounds__(256) void logits_kernel(
    const __half* __restrict__ X, const float* __restrict__ Wt,
    const float* __restrict__ mask, float* __restrict__ logits)
{
    const int m = blockIdx.x;
    const int b = m >> 11;
    const int s = m & (SS - 1);
    const int tid = threadIdx.x;

    __shared__ float xs[DD];
    __shared__ float red[256];

    {
        const uint2 hv = ((const uint2*)(X + (size_t)m * DD))[tid];
        const __half2* hp = (const __half2*)&hv;
        float2 f0 = __half22float2(hp[0]);
        float2 f1 = __half22float2(hp[1]);
        ((float4*)xs)[tid] = make_float4(f0.x, f0.y, f1.x, f1.y);
    }
    __syncthreads();

    const int h = tid >> 4, g = tid & 15;
    const float* wrow = Wt + h * DD;
    float acc = 0.f;
    #pragma unroll 8
    for (int j = 0; j < 64; j++)
        acc += xs[g + 16 * j] * wrow[g + 16 * j];

    red[tid] = acc;
    __syncthreads();
    if (tid < HH) {
        float v = 0.f;
        #pragma unroll
        for (int g2 = 0; g2 < 16; g2++) v += red[tid * 16 + g2];
        logits[((size_t)(b * HH + tid)) * SS + s] =
            v * 0.125f - (1.f - mask[m]) * 1e8f;
    }
}

// fused k logits: row s' of QK_flat gathered from fp16 K scaled by gq.
__global__ __launch_bounds__(256) void k_logits_kernel(
    const __half* __restrict__ K, const float* __restrict__ gq,
    const float* __restrict__ Wt, const float* __restrict__ mask,
    float* __restrict__ logits)
{
    const int m = blockIdx.x;
    const int b = m >> 11;
    const int s = m & (SS - 1);
    const int hp = s >> 7;
    const int sbase = (s & 127) * 16;
    const int tid = threadIdx.x;

    __shared__ float xs[DD];
    __shared__ float red[256];

    // vectorized gather: 4 halfs per thread (8B aligned)
    {
        const int j = tid >> 4;                // 0..15
        const int dh0 = (tid & 15) * 4;        // 0..60
        const float* gqr = gq + (size_t)(b * HH + hp) * DHH + dh0;
        const uint2 hv = *(const uint2*)(K + ((size_t)(b * SS + sbase + j)) * DD
                                           + hp * DHH + dh0);
        const __half2* hpv = (const __half2*)&hv;
        float2 f0 = __half22float2(hpv[0]);
        float2 f1 = __half22float2(hpv[1]);
        xs[j * 64 + dh0 + 0] = f0.x * gqr[0];
        xs[j * 64 + dh0 + 1] = f0.y * gqr[1];
        xs[j * 64 + dh0 + 2] = f1.x * gqr[2];
        xs[j * 64 + dh0 + 3] = f1.y * gqr[3];
    }
    __syncthreads();

    const int h = tid >> 4, g = tid & 15;
    const float* wrow = Wt + h * DD;
    float acc = 0.f;
    #pragma unroll 8
    for (int j = 0; j < 64; j++)
        acc += xs[g + 16 * j] * wrow[g + 16 * j];

    red[tid] = acc;
    __syncthreads();
    if (tid < HH) {
        float v = 0.f;
        #pragma unroll
        for (int g2 = 0; g2 < 16; g2++) v += red[tid * 16 + g2];
        logits[((size_t)(b * HH + tid)) * SS + s] =
            v * 0.125f - (1.f - mask[m]) * 1e8f;
    }
}

// att = softmax(logits[b,h,:]); gout = (gmul?) * sum_s att[s]*src.
// 512 threads; phase 3 is warp-per-row: warp w covers s = w, w+16, ...,
// lane l reads the half2 at dh=2l  =>  one contiguous 128B segment per row.
template<bool GM>
__global__ __launch_bounds__(512) void softmax_wsum_kernel(
    const float* __restrict__ logits, const __half* __restrict__ src,
    float* __restrict__ gout, const float* __restrict__ gmul)
{
    const int b = blockIdx.x >> 4, h = blockIdx.x & 15;
    const int tid = threadIdx.x;
    const float* lrow = logits + (size_t)(b * HH + h) * SS;

    __shared__ float att[SS];        // 8 KB
    __shared__ float red[1024];      // 4 KB (softmax reduce + 16x64 wsum tile)

    float mx = -3.4e38f;
    for (int s = tid; s < SS; s += 512) mx = fmaxf(mx, lrow[s]);
    red[tid] = mx; __syncthreads();
    for (int off = 256; off > 0; off >>= 1) {
        if (tid < off) red[tid] = fmaxf(red[tid], red[tid + off]);
        __syncthreads();
    }
    mx = red[0];
    __syncthreads();

    float sum = 0.f;
    for (int s = tid; s < SS; s += 512) {
        float e = expf(lrow[s] - mx);
        att[s] = e;
        sum += e;
    }
    red[tid] = sum; __syncthreads();
    for (int off = 256; off > 0; off >>= 1) {
        if (tid < off) red[tid] += red[tid + off];
        __syncthreads();
    }
    const float inv = 1.f / red[0];
    __syncthreads();

    // ---- coalesced weighted sum: warp-per-row
    const int w = tid >> 5, l = tid & 31;
    const __half* base = src + (size_t)b * (SS * DD) + h * DHH + 2 * l;
    float2 acc = make_float2(0.f, 0.f);
    #pragma unroll 4
    for (int s = w; s < SS; s += 16) {
        const float a = att[s];
        const float2 f = __half22float2(*(const __half2*)(base + (size_t)s * DD));
        acc.x += a * f.x;
        acc.y += a * f.y;
    }
    red[w * 64 + 2 * l]     = acc.x;
    red[w * 64 + 2 * l + 1] = acc.y;
    __syncthreads();

    if (tid < DHH) {
        float v = 0.f;
        #pragma unroll
        for (int jj = 0; jj < 16; jj++) v += red[jj * 64 + tid];
        float r = v * inv;
        if (GM) r *= gmul[(b * HH + h) * DHH + tid];
        gout[(b * HH + h) * DHH + tid] = r;
    }
}

// ===========================================================================
extern "C" void kernel_launch(void* const* d_in, const int* in_sizes, int n_in,
                              void* d_out, int out_size)
{
    const float* Qseq  = (const float*)d_in[0];
    const float* Kseq  = (const float*)d_in[1];
    const float* Qmask = (const float*)d_in[2];
    const float* Kmask = (const float*)d_in[3];
    const float* WQ    = (const float*)d_in[4];
    const float* WK    = (const float*)d_in[5];
    const float* Wq    = (const float*)d_in[6];
    const float* Wk    = (const float*)d_in[7];
    const float* WP    = (const float*)d_in[8];
    float* out = (float*)d_out;

    float *pL, *pgq, *pgk, *pWt;
    __half *pQh, *pKh, *pA, *pB, *pBP;
    cudaGetSymbolAddress((void**)&pQh, g_Qh);
    cudaGetSymbolAddress((void**)&pKh, g_Kh);
    cudaGetSymbolAddress((void**)&pL,  g_logits);
    cudaGetSymbolAddress((void**)&pgq, g_gq);
    cudaGetSymbolAddress((void**)&pgk, g_gk);
    cudaGetSymbolAddress((void**)&pWt, g_Wt);
    cudaGetSymbolAddress((void**)&pA,  g_Af16);
    cudaGetSymbolAddress((void**)&pB,  g_Bf16);
    cudaGetSymbolAddress((void**)&pBP, g_BP);

    cudaFuncSetAttribute(hmma_gemm_kernel<false>,
                         cudaFuncAttributeMaxDynamicSharedMemorySize, GEMM_SMEM);
    cudaFuncSetAttribute(hmma_gemm_kernel<true>,
                         cudaFuncAttributeMaxDynamicSharedMemorySize, GEMM_SMEM);

    const int spB = (MM * DD) / 8 / 256;   // 8192 blocks per input

    // 0) transpose Wq/Wk for the logits kernels
    wtrans_kernel<<<dim3(64, 2), 256>>>(Wq, Wk, pWt);

    // 1+2) Q = Q_seq @ WQ and K = K_seq @ WK  (merged, fp16 outputs)
    tohalf_kernel<<<dim3(spB, 2), 256>>>(Qseq, Kseq, pA);
    wsplit_kernel<<<dim3(32, 32, 2), 256>>>(WQ, WK, pB);
    hmma_gemm_kernel<false><<<dim3(8, 128, 2), 256, GEMM_SMEM>>>(
        pA, pB, pQh, pKh, nullptr, nullptr);

    // 3) q logits + softmax + global_q
    logits_kernel<<<MM, 256>>>(pQh, pWt, Qmask, pL);
    softmax_wsum_kernel<false><<<BB * HH, 512>>>(pL, pQh, pgq, nullptr);

    // 4) k logits (fused QK gather) + softmax + global_k (fused gq mul)
    k_logits_kernel<<<MM, 256>>>(pKh, pgq, pWt + HH * DD, Kmask, pL);
    softmax_wsum_kernel<true><<<BB * HH, 512>>>(pL, pKh, pgk, pgq);

    // 5) out = Q @ (diag(gk_b)·WP) + Q   (gk folded into per-batch B)
    wpscale_kernel<<<dim3(32, 32, 8), 256>>>(WP, pgk, pBP);
    hmma_gemm_kernel<true><<<dim3(8, 128, 1), 256, GEMM_SMEM>>>(
        pQh, pBP, nullptr, nullptr, out, pQh);
}

// round 15
// speedup vs baseline: 1.0217x; 1.0217x over previous
#include <cuda_runtime.h>
#include <cuda_fp16.h>
#include <math.h>
#include <stdint.h>

// Problem constants
#define BB   8
#define SS   2048
#define HH   16
#define DHH  64
#define DD   1024            // H*DH
#define MM   (BB*SS)         // 16384

#define WSCALE     256.0f
#define WSCALE_INV 0.00390625f

// ---------------- scratch (__device__ globals; allocation-free) -------------
__device__ __half g_Qh   [MM*DD];        // Q = Q_seq @ WQ  (fp16)
__device__ __half g_Kh   [MM*DD];        // K = K_seq @ WK  (fp16)
__device__ float g_logits[BB*HH*SS];     // (B,H,S)
__device__ float g_gq    [BB*HH*DHH];
__device__ float g_gk    [BB*HH*DHH];
__device__ float g_Wt    [2*HH*DD];      // transposed Wq (slot0) / Wk (slot1)
__device__ __half g_Af16[2*MM*DD];       // fp16 A (2 slots for merged GEMM1/2)
__device__ __half g_Bf16[2*DD*DD];       // transposed weights Bt[n,k], x256, fp16
__device__ __half g_BP  [BB*DD*DD];      // per-batch gk-scaled WPt[n,k], x256, fp16

// ======================= PTX helpers ========================================
__device__ __forceinline__ uint32_t smem_to_u32(const void* p) {
    uint32_t a;
    asm("{ .reg .u64 t; cvta.to.shared.u64 t, %1; cvt.u32.u64 %0, t; }"
        : "=r"(a) : "l"(p));
    return a;
}
#define LDSM4(r, addr) asm volatile( \
    "ldmatrix.sync.aligned.m8n8.x4.shared.b16 {%0,%1,%2,%3}, [%4];" \
    : "=r"((r)[0]), "=r"((r)[1]), "=r"((r)[2]), "=r"((r)[3]) : "r"(addr))
#define MMA_F16(d, a, b) asm volatile( \
    "mma.sync.aligned.m16n8k16.row.col.f32.f16.f16.f32 " \
    "{%0,%1,%2,%3}, {%4,%5,%6,%7}, {%8,%9}, {%0,%1,%2,%3};" \
    : "+f"((d)[0]), "+f"((d)[1]), "+f"((d)[2]), "+f"((d)[3]) \
    : "r"((a)[0]), "r"((a)[1]), "r"((a)[2]), "r"((a)[3]), \
      "r"((b)[0]), "r"((b)[1]))
__device__ __forceinline__ void cp16(uint32_t dst, const void* src) {
    asm volatile("cp.async.cg.shared.global [%0], [%1], 16;"
                 :: "r"(dst), "l"(src) : "memory");
}
#define CP_COMMIT()  asm volatile("cp.async.commit_group;" ::: "memory")
#define CP_WAIT_1()  asm volatile("cp.async.wait_group 1;" ::: "memory")
#define CP_WAIT_0()  asm volatile("cp.async.wait_group 0;" ::: "memory")

__device__ __forceinline__ uint32_t pack_h(float a, float b) {
    __half2 t;
    t.x = __float2half_rn(a);
    t.y = __float2half_rn(b);
    return *(uint32_t*)&t;
}

// ======================= HMMA fp16 GEMM =====================================
// acc = (1/256) * Af16 @ Bf16, B pre-scaled x256.
// CTA tile 128x64, BK=64, 8 warps (warp 32x32), 3-stage cp.async pipeline,
// XOR-swizzled 128B rows, 3 CTAs/SM (reg cap 85, smem 24KB/stage).
// Stage: A [128][128B] @0 (16KB), B [64][128B] @16384 (8KB)
#define NST       3
#define STAGE_B   24576
#define GEMM_SMEM (NST * STAGE_B)     // 73728
#define KB2       16                  // 1024 / 64

template<bool RES>
__global__ __launch_bounds__(256, 3) void hmma_gemm_kernel(
    const __half* __restrict__ A, const __half* __restrict__ B,
    __half* __restrict__ H0, __half* __restrict__ H1,
    float* __restrict__ F, const __half* __restrict__ res)
{
    extern __shared__ __align__(128) char smem[];
    const uint32_t sb = smem_to_u32(smem);
    const int tid = threadIdx.x;
    const int lane = tid & 31;
    const int wid  = tid >> 5;
    const int warpM = wid >> 1;            // 0..3 (32 rows each)
    const int warpN = wid & 1;             // 0..1 (32 cols each)
    const int colBase = blockIdx.x * 64;
    const int rowBase = blockIdx.y * 128;
    const int z = blockIdx.z;
    const size_t aZ = (size_t)z * MM * DD;
    const size_t bZ = RES ? (size_t)(blockIdx.y >> 4) * DD * DD
                          : (size_t)z * DD * DD;

    // ---- cp.async mapping
    // A: 128 rows x 128B; row = tid>>1, half = tid&1, 4 chunks of 16B
    const int crow = tid >> 1;
    const int half = tid & 1;
    const int rswA = crow & 7;
    uint32_t dA[4];
    #pragma unroll
    for (int i = 0; i < 4; i++)
        dA[i] = crow * 128 + (((half * 4 + i) ^ rswA) << 4);
    const char* pA = (const char*)(A + aZ + (size_t)(rowBase + crow) * DD) + half * 64;
    // B: 64 rows x 128B; row = tid>>2, q = tid&3, 2 chunks of 16B
    const int brow = tid >> 2;
    const int bq   = tid & 3;
    const int rswB = brow & 7;
    uint32_t dB[2];
    #pragma unroll
    for (int i = 0; i < 2; i++)
        dB[i] = brow * 128 + (((bq * 2 + i) ^ rswB) << 4);
    const char* pB = (const char*)(B + bZ + (size_t)(colBase + brow) * DD) + bq * 32;

    #define ISSUE(s, kb) do {                                              \
        const uint32_t bs_ = sb + (s) * STAGE_B;                           \
        const int ko_ = (kb) * 128;                                        \
        _Pragma("unroll")                                                  \
        for (int i = 0; i < 4; i++)                                        \
            cp16(bs_ + dA[i], pA + ko_ + i * 16);                          \
        _Pragma("unroll")                                                  \
        for (int i = 0; i < 2; i++)                                        \
            cp16(bs_ + 16384 + dB[i], pB + ko_ + i * 16);                  \
        CP_COMMIT();                                                       \
    } while (0)

    // ---- ldmatrix row bases + swizzle keys
    const int lrow = lane & 15;
    const int hi16 = lane >> 4;
    uint32_t aRow[2]; int aSw[2];
    #pragma unroll
    for (int mf = 0; mf < 2; mf++) {
        const int r = warpM * 32 + mf * 16 + lrow;
        aRow[mf] = r * 128; aSw[mf] = r & 7;
    }
    uint32_t bRow[2]; int bSw[2];
    #pragma unroll
    for (int np = 0; np < 2; np++) {
        const int r = warpN * 32 + np * 16 + lrow;
        bRow[np] = r * 128; bSw[np] = r & 7;
    }

    ISSUE(0, 0);
    ISSUE(1, 1);

    float acc[2][4][4];
    #pragma unroll
    for (int mf = 0; mf < 2; mf++)
        #pragma unroll
        for (int nf = 0; nf < 4; nf++)
            #pragma unroll
            for (int q = 0; q < 4; q++) acc[mf][nf][q] = 0.f;

    for (int kb = 0; kb < KB2; kb++) {
        if (kb == KB2 - 1) { CP_WAIT_0(); } else { CP_WAIT_1(); }
        __syncthreads();
        if (kb + 2 < KB2) ISSUE((kb + 2) % NST, kb + 2);

        const uint32_t st = sb + (kb % NST) * STAGE_B;
        #pragma unroll
        for (int ks = 0; ks < 4; ks++) {
            const int ck = ks * 2 + hi16;
            uint32_t b0[4][2];
            #pragma unroll
            for (int np = 0; np < 2; np++) {
                uint32_t r[4];
                LDSM4(r, st + 16384 + bRow[np] + (((ck ^ bSw[np])) << 4));
                b0[np * 2 + 0][0] = r[0]; b0[np * 2 + 0][1] = r[2];
                b0[np * 2 + 1][0] = r[1]; b0[np * 2 + 1][1] = r[3];
            }
            uint32_t a[2][4];
            #pragma unroll
            for (int mf = 0; mf < 2; mf++)
                LDSM4(a[mf], st + aRow[mf] + (((ck ^ aSw[mf])) << 4));
            #pragma unroll
            for (int mf = 0; mf < 2; mf++)
                #pragma unroll
                for (int nf = 0; nf < 4; nf++)
                    MMA_F16(acc[mf][nf], a[mf], b0[nf]);
        }
    }
    #undef ISSUE

    // ---- epilogue (undo x256 weight scale)
    const int er = lane >> 2;
    const int ec = (lane & 3) * 2;
    __half* Hout = z ? H1 : H0;
    #pragma unroll
    for (int mf = 0; mf < 2; mf++) {
        const int row0 = rowBase + warpM * 32 + mf * 16 + er;
        #pragma unroll
        for (int nf = 0; nf < 4; nf++) {
            const int col = colBase + warpN * 32 + nf * 8 + ec;
            const float a0 = acc[mf][nf][0] * WSCALE_INV;
            const float a1 = acc[mf][nf][1] * WSCALE_INV;
            const float a2 = acc[mf][nf][2] * WSCALE_INV;
            const float a3 = acc[mf][nf][3] * WSCALE_INV;
            if (RES) {
                const __half2 r0 = *(const __half2*)(res + (size_t)row0 * DD + col);
                const __half2 r1 = *(const __half2*)(res + (size_t)(row0 + 8) * DD + col);
                float2 v0 = make_float2(a0 + __half2float(r0.x), a1 + __half2float(r0.y));
                float2 v1 = make_float2(a2 + __half2float(r1.x), a3 + __half2float(r1.y));
                *(float2*)(F + (size_t)row0 * DD + col) = v0;
                *(float2*)(F + (size_t)(row0 + 8) * DD + col) = v1;
            } else {
                *(uint32_t*)(Hout + (size_t)row0 * DD + col) = pack_h(a0, a1);
                *(uint32_t*)(Hout + (size_t)(row0 + 8) * DD + col) = pack_h(a2, a3);
            }
        }
    }
}

// ======================= A conversion (fp32 -> fp16) ========================
__global__ __launch_bounds__(256) void tohalf_kernel(
    const float* __restrict__ in0, const float* __restrict__ in1,
    __half* __restrict__ o)
{
    const size_t e = ((size_t)blockIdx.x * 256 + threadIdx.x) * 8;
    const float* in = blockIdx.y ? in1 : in0;
    const size_t oz = (size_t)blockIdx.y * ((size_t)MM * DD);
    float4 v0 = *(const float4*)(in + e);
    float4 v1 = *(const float4*)(in + e + 4);
    uint4 h = make_uint4(pack_h(v0.x, v0.y), pack_h(v0.z, v0.w),
                         pack_h(v1.x, v1.y), pack_h(v1.z, v1.w));
    *(uint4*)(o + oz + e) = h;
}

// ======================= weight transpose (x256, fp16) ======================
__global__ __launch_bounds__(256) void wsplit_kernel(
    const float* __restrict__ W0, const float* __restrict__ W1,
    __half* __restrict__ bh)
{
    __shared__ float tile[32][33];
    const float* W = blockIdx.z ? W1 : W0;
    const size_t oz = (size_t)blockIdx.z * DD * DD;
    const int tx = threadIdx.x & 31, ty0 = threadIdx.x >> 5;
    const int nbase = blockIdx.x * 32, kbase = blockIdx.y * 32;
    #pragma unroll
    for (int j = 0; j < 4; j++) {
        int r = ty0 + j * 8;
        tile[r][tx] = W[(size_t)(kbase + r) * DD + nbase + tx];
    }
    __syncthreads();
    #pragma unroll
    for (int j = 0; j < 4; j++) {
        int n = nbase + ty0 + j * 8;
        int k = kbase + tx;
        bh[oz + (size_t)n * DD + k] = __float2half_rn(tile[tx][ty0 + j * 8] * WSCALE);
    }
}

// ======= per-batch gk-scaled WP transpose: BP[b][n][k] = WP[k][n]*gk[b,k]*256
__global__ __launch_bounds__(256) void wpscale_kernel(
    const float* __restrict__ WP, const float* __restrict__ gk,
    __half* __restrict__ bp)
{
    __shared__ float tile[32][33];
    const int b = blockIdx.z;
    const size_t oz = (size_t)b * DD * DD;
    const int tx = threadIdx.x & 31, ty0 = threadIdx.x >> 5;
    const int nbase = blockIdx.x * 32, kbase = blockIdx.y * 32;
    #pragma unroll
    for (int j = 0; j < 4; j++) {
        int r = ty0 + j * 8;
        tile[r][tx] = WP[(size_t)(kbase + r) * DD + nbase + tx];
    }
    __syncthreads();
    const float gv = gk[b * DD + kbase + tx] * WSCALE;
    #pragma unroll
    for (int j = 0; j < 4; j++) {
        int n = nbase + ty0 + j * 8;
        int k = kbase + tx;
        bp[oz + (size_t)n * DD + k] = __float2half_rn(tile[tx][ty0 + j * 8] * gv);
    }
}

// ======================= small-W transpose (Wq/Wk -> Wt[h][d]) ==============
__global__ __launch_bounds__(256) void wtrans_kernel(
    const float* __restrict__ W0, const float* __restrict__ W1,
    float* __restrict__ Wt)
{
    const int idx = blockIdx.x * 256 + threadIdx.x;      // 0..16383
    const float* W = blockIdx.y ? W1 : W0;
    const int h = idx >> 10, d = idx & (DD - 1);
    Wt[blockIdx.y * (HH * DD) + idx] = W[d * HH + h];
}

// ======================= middle kernels =====================================
__global__ __launch_bounds__(256) void logits_kernel(
    const __half* __restrict__ X, const float* __restrict__ Wt,
    const float* __restrict__ mask, float* __restrict__ logits)
{
    const int m = blockIdx.x;
    const int b = m >> 11;
    const int s = m & (SS - 1);
    const int tid = threadIdx.x;

    __shared__ float xs[DD];
    __shared__ float red[256];

    {
        const uint2 hv = ((const uint2*)(X + (size_t)m * DD))[tid];
        const __half2* hp = (const __half2*)&hv;
        float2 f0 = __half22float2(hp[0]);
        float2 f1 = __half22float2(hp[1]);
        ((float4*)xs)[tid] = make_float4(f0.x, f0.y, f1.x, f1.y);
    }
    __syncthreads();

    const int h = tid >> 4, g = tid & 15;
    const float* wrow = Wt + h * DD;
    float acc = 0.f;
    #pragma unroll 8
    for (int j = 0; j < 64; j++)
        acc += xs[g + 16 * j] * wrow[g + 16 * j];

    red[tid] = acc;
    __syncthreads();
    if (tid < HH) {
        float v = 0.f;
        #pragma unroll
        for (int g2 = 0; g2 < 16; g2++) v += red[tid * 16 + g2];
        logits[((size_t)(b * HH + tid)) * SS + s] =
            v * 0.125f - (1.f - mask[m]) * 1e8f;
    }
}

// fused k logits: row s' of QK_flat gathered from fp16 K scaled by gq.
__global__ __launch_bounds__(256) void k_logits_kernel(
    const __half* __restrict__ K, const float* __restrict__ gq,
    const float* __restrict__ Wt, const float* __restrict__ mask,
    float* __restrict__ logits)
{
    const int m = blockIdx.x;
    const int b = m >> 11;
    const int s = m & (SS - 1);
    const int hp = s >> 7;
    const int sbase = (s & 127) * 16;
    const int tid = threadIdx.x;

    __shared__ float xs[DD];
    __shared__ float red[256];

    // vectorized gather: 4 halfs per thread (8B aligned)
    {
        const int j = tid >> 4;                // 0..15
        const int dh0 = (tid & 15) * 4;        // 0..60
        const float* gqr = gq + (size_t)(b * HH + hp) * DHH + dh0;
        const uint2 hv = *(const uint2*)(K + ((size_t)(b * SS + sbase + j)) * DD
                                           + hp * DHH + dh0);
        const __half2* hpv = (const __half2*)&hv;
        float2 f0 = __half22float2(hpv[0]);
        float2 f1 = __half22float2(hpv[1]);
        xs[j * 64 + dh0 + 0] = f0.x * gqr[0];
        xs[j * 64 + dh0 + 1] = f0.y * gqr[1];
        xs[j * 64 + dh0 + 2] = f1.x * gqr[2];
        xs[j * 64 + dh0 + 3] = f1.y * gqr[3];
    }
    __syncthreads();

    const int h = tid >> 4, g = tid & 15;
    const float* wrow = Wt + h * DD;
    float acc = 0.f;
    #pragma unroll 8
    for (int j = 0; j < 64; j++)
        acc += xs[g + 16 * j] * wrow[g + 16 * j];

    red[tid] = acc;
    __syncthreads();
    if (tid < HH) {
        float v = 0.f;
        #pragma unroll
        for (int g2 = 0; g2 < 16; g2++) v += red[tid * 16 + g2];
        logits[((size_t)(b * HH + tid)) * SS + s] =
            v * 0.125f - (1.f - mask[m]) * 1e8f;
    }
}

// att = softmax(logits[b,h,:]); gout = (gmul?) * sum_s att[s]*src.
// 512 threads; phase 3 warp-per-row (coalesced 128B rows).
template<bool GM>
__global__ __launch_bounds__(512) void softmax_wsum_kernel(
    const float* __restrict__ logits, const __half* __restrict__ src,
    float* __restrict__ gout, const float* __restrict__ gmul)
{
    const int b = blockIdx.x >> 4, h = blockIdx.x & 15;
    const int tid = threadIdx.x;
    const float* lrow = logits + (size_t)(b * HH + h) * SS;

    __shared__ float att[SS];        // 8 KB
    __shared__ float red[1024];      // 4 KB

    float mx = -3.4e38f;
    for (int s = tid; s < SS; s += 512) mx = fmaxf(mx, lrow[s]);
    red[tid] = mx; __syncthreads();
    for (int off = 256; off > 0; off >>= 1) {
        if (tid < off) red[tid] = fmaxf(red[tid], red[tid + off]);
        __syncthreads();
    }
    mx = red[0];
    __syncthreads();

    float sum = 0.f;
    for (int s = tid; s < SS; s += 512) {
        float e = expf(lrow[s] - mx);
        att[s] = e;
        sum += e;
    }
    red[tid] = sum; __syncthreads();
    for (int off = 256; off > 0; off >>= 1) {
        if (tid < off) red[tid] += red[tid + off];
        __syncthreads();
    }
    const float inv = 1.f / red[0];
    __syncthreads();

    const int w = tid >> 5, l = tid & 31;
    const __half* base = src + (size_t)b * (SS * DD) + h * DHH + 2 * l;
    float2 acc = make_float2(0.f, 0.f);
    #pragma unroll 4
    for (int s = w; s < SS; s += 16) {
        const float a = att[s];
        const float2 f = __half22float2(*(const __half2*)(base + (size_t)s * DD));
        acc.x += a * f.x;
        acc.y += a * f.y;
    }
    red[w * 64 + 2 * l]     = acc.x;
    red[w * 64 + 2 * l + 1] = acc.y;
    __syncthreads();

    if (tid < DHH) {
        float v = 0.f;
        #pragma unroll
        for (int jj = 0; jj < 16; jj++) v += red[jj * 64 + tid];
        float r = v * inv;
        if (GM) r *= gmul[(b * HH + h) * DHH + tid];
        gout[(b * HH + h) * DHH + tid] = r;
    }
}

// ===========================================================================
extern "C" void kernel_launch(void* const* d_in, const int* in_sizes, int n_in,
                              void* d_out, int out_size)
{
    const float* Qseq  = (const float*)d_in[0];
    const float* Kseq  = (const float*)d_in[1];
    const float* Qmask = (const float*)d_in[2];
    const float* Kmask = (const float*)d_in[3];
    const float* WQ    = (const float*)d_in[4];
    const float* WK    = (const float*)d_in[5];
    const float* Wq    = (const float*)d_in[6];
    const float* Wk    = (const float*)d_in[7];
    const float* WP    = (const float*)d_in[8];
    float* out = (float*)d_out;

    float *pL, *pgq, *pgk, *pWt;
    __half *pQh, *pKh, *pA, *pB, *pBP;
    cudaGetSymbolAddress((void**)&pQh, g_Qh);
    cudaGetSymbolAddress((void**)&pKh, g_Kh);
    cudaGetSymbolAddress((void**)&pL,  g_logits);
    cudaGetSymbolAddress((void**)&pgq, g_gq);
    cudaGetSymbolAddress((void**)&pgk, g_gk);
    cudaGetSymbolAddress((void**)&pWt, g_Wt);
    cudaGetSymbolAddress((void**)&pA,  g_Af16);
    cudaGetSymbolAddress((void**)&pB,  g_Bf16);
    cudaGetSymbolAddress((void**)&pBP, g_BP);

    cudaFuncSetAttribute(hmma_gemm_kernel<false>,
                         cudaFuncAttributeMaxDynamicSharedMemorySize, GEMM_SMEM);
    cudaFuncSetAttribute(hmma_gemm_kernel<true>,
                         cudaFuncAttributeMaxDynamicSharedMemorySize, GEMM_SMEM);

    const int spB = (MM * DD) / 8 / 256;   // 8192 blocks per input

    // 0) transpose Wq/Wk for the logits kernels
    wtrans_kernel<<<dim3(64, 2), 256>>>(Wq, Wk, pWt);

    // 1+2) Q = Q_seq @ WQ and K = K_seq @ WK  (merged, fp16 outputs)
    tohalf_kernel<<<dim3(spB, 2), 256>>>(Qseq, Kseq, pA);
    wsplit_kernel<<<dim3(32, 32, 2), 256>>>(WQ, WK, pB);
    hmma_gemm_kernel<false><<<dim3(16, 128, 2), 256, GEMM_SMEM>>>(
        pA, pB, pQh, pKh, nullptr, nullptr);

    // 3) q logits + softmax + global_q
    logits_kernel<<<MM, 256>>>(pQh, pWt, Qmask, pL);
    softmax_wsum_kernel<false><<<BB * HH, 512>>>(pL, pQh, pgq, nullptr);

    // 4) k logits (fused QK gather) + softmax + global_k (fused gq mul)
    k_logits_kernel<<<MM, 256>>>(pKh, pgq, pWt + HH * DD, Kmask, pL);
    softmax_wsum_kernel<true><<<BB * HH, 512>>>(pL, pKh, pgk, pgq);

    // 5) out = Q @ (diag(gk_b)·WP) + Q   (gk folded into per-batch B)
    wpscale_kernel<<<dim3(32, 32, 8), 256>>>(WP, pgk, pBP);
    hmma_gemm_kernel<true><<<dim3(16, 128, 1), 256, GEMM_SMEM>>>(
        pQh, pBP, nullptr, nullptr, out, pQh);
}

// round 16
// speedup vs baseline: 1.1920x; 1.1667x over previous
#include <cuda_runtime.h>
#include <cuda_fp16.h>
#include <math.h>
#include <stdint.h>

// Problem constants
#define BB   8
#define SS   2048
#define HH   16
#define DHH  64
#define DD   1024            // H*DH
#define MM   (BB*SS)         // 16384

#define WSCALE     256.0f
#define WSCALE_INV 0.00390625f

// ---------------- scratch (__device__ globals; allocation-free) -------------
__device__ __half g_Qh   [MM*DD];        // Q = Q_seq @ WQ  (fp16)
__device__ __half g_Kh   [MM*DD];        // K = K_seq @ WK  (fp16)
__device__ float g_logits[BB*HH*SS];     // (B,H,S)
__device__ float g_gq    [BB*HH*DHH];
__device__ float g_gk    [BB*HH*DHH];
__device__ float g_Wt    [2*HH*DD];      // transposed Wq (slot0) / Wk (slot1)
__device__ __half g_Af16[2*MM*DD];       // fp16 A (2 slots for merged GEMM1/2)
__device__ __half g_Bf16[2*DD*DD];       // transposed weights Bt[n,k], x256, fp16
__device__ __half g_BP  [BB*DD*DD];      // per-batch gk-scaled WPt[n,k], x256, fp16

// ======================= PTX helpers ========================================
__device__ __forceinline__ uint32_t smem_to_u32(const void* p) {
    uint32_t a;
    asm("{ .reg .u64 t; cvta.to.shared.u64 t, %1; cvt.u32.u64 %0, t; }"
        : "=r"(a) : "l"(p));
    return a;
}
#define LDSM4(r, addr) asm volatile( \
    "ldmatrix.sync.aligned.m8n8.x4.shared.b16 {%0,%1,%2,%3}, [%4];" \
    : "=r"((r)[0]), "=r"((r)[1]), "=r"((r)[2]), "=r"((r)[3]) : "r"(addr))
#define MMA_F16(d, a, b) asm volatile( \
    "mma.sync.aligned.m16n8k16.row.col.f32.f16.f16.f32 " \
    "{%0,%1,%2,%3}, {%4,%5,%6,%7}, {%8,%9}, {%0,%1,%2,%3};" \
    : "+f"((d)[0]), "+f"((d)[1]), "+f"((d)[2]), "+f"((d)[3]) \
    : "r"((a)[0]), "r"((a)[1]), "r"((a)[2]), "r"((a)[3]), \
      "r"((b)[0]), "r"((b)[1]))
__device__ __forceinline__ void cp16(uint32_t dst, const void* src) {
    asm volatile("cp.async.cg.shared.global [%0], [%1], 16;"
                 :: "r"(dst), "l"(src) : "memory");
}
#define CP_COMMIT()  asm volatile("cp.async.commit_group;" ::: "memory")
#define CP_WAIT_1()  asm volatile("cp.async.wait_group 1;" ::: "memory")
#define CP_WAIT_0()  asm volatile("cp.async.wait_group 0;" ::: "memory")

__device__ __forceinline__ uint32_t pack_h(float a, float b) {
    __half2 t;
    t.x = __float2half_rn(a);
    t.y = __float2half_rn(b);
    return *(uint32_t*)&t;
}

// ======================= HMMA fp16 GEMM (unchanged from R15) ================
#define NST       3
#define STAGE_B   24576
#define GEMM_SMEM (NST * STAGE_B)     // 73728
#define KB2       16                  // 1024 / 64

template<bool RES>
__global__ __launch_bounds__(256, 3) void hmma_gemm_kernel(
    const __half* __restrict__ A, const __half* __restrict__ B,
    __half* __restrict__ H0, __half* __restrict__ H1,
    float* __restrict__ F, const __half* __restrict__ res)
{
    extern __shared__ __align__(128) char smem[];
    const uint32_t sb = smem_to_u32(smem);
    const int tid = threadIdx.x;
    const int lane = tid & 31;
    const int wid  = tid >> 5;
    const int warpM = wid >> 1;            // 0..3 (32 rows each)
    const int warpN = wid & 1;             // 0..1 (32 cols each)
    const int colBase = blockIdx.x * 64;
    const int rowBase = blockIdx.y * 128;
    const int z = blockIdx.z;
    const size_t aZ = (size_t)z * MM * DD;
    const size_t bZ = RES ? (size_t)(blockIdx.y >> 4) * DD * DD
                          : (size_t)z * DD * DD;

    const int crow = tid >> 1;
    const int half = tid & 1;
    const int rswA = crow & 7;
    uint32_t dA[4];
    #pragma unroll
    for (int i = 0; i < 4; i++)
        dA[i] = crow * 128 + (((half * 4 + i) ^ rswA) << 4);
    const char* pA = (const char*)(A + aZ + (size_t)(rowBase + crow) * DD) + half * 64;
    const int brow = tid >> 2;
    const int bq   = tid & 3;
    const int rswB = brow & 7;
    uint32_t dB[2];
    #pragma unroll
    for (int i = 0; i < 2; i++)
        dB[i] = brow * 128 + (((bq * 2 + i) ^ rswB) << 4);
    const char* pB = (const char*)(B + bZ + (size_t)(colBase + brow) * DD) + bq * 32;

    #define ISSUE(s, kb) do {                                              \
        const uint32_t bs_ = sb + (s) * STAGE_B;                           \
        const int ko_ = (kb) * 128;                                        \
        _Pragma("unroll")                                                  \
        for (int i = 0; i < 4; i++)                                        \
            cp16(bs_ + dA[i], pA + ko_ + i * 16);                          \
        _Pragma("unroll")                                                  \
        for (int i = 0; i < 2; i++)                                        \
            cp16(bs_ + 16384 + dB[i], pB + ko_ + i * 16);                  \
        CP_COMMIT();                                                       \
    } while (0)

    const int lrow = lane & 15;
    const int hi16 = lane >> 4;
    uint32_t aRow[2]; int aSw[2];
    #pragma unroll
    for (int mf = 0; mf < 2; mf++) {
        const int r = warpM * 32 + mf * 16 + lrow;
        aRow[mf] = r * 128; aSw[mf] = r & 7;
    }
    uint32_t bRow[2]; int bSw[2];
    #pragma unroll
    for (int np = 0; np < 2; np++) {
        const int r = warpN * 32 + np * 16 + lrow;
        bRow[np] = r * 128; bSw[np] = r & 7;
    }

    ISSUE(0, 0);
    ISSUE(1, 1);

    float acc[2][4][4];
    #pragma unroll
    for (int mf = 0; mf < 2; mf++)
        #pragma unroll
        for (int nf = 0; nf < 4; nf++)
            #pragma unroll
            for (int q = 0; q < 4; q++) acc[mf][nf][q] = 0.f;

    for (int kb = 0; kb < KB2; kb++) {
        if (kb == KB2 - 1) { CP_WAIT_0(); } else { CP_WAIT_1(); }
        __syncthreads();
        if (kb + 2 < KB2) ISSUE((kb + 2) % NST, kb + 2);

        const uint32_t st = sb + (kb % NST) * STAGE_B;
        #pragma unroll
        for (int ks = 0; ks < 4; ks++) {
            const int ck = ks * 2 + hi16;
            uint32_t b0[4][2];
            #pragma unroll
            for (int np = 0; np < 2; np++) {
                uint32_t r[4];
                LDSM4(r, st + 16384 + bRow[np] + (((ck ^ bSw[np])) << 4));
                b0[np * 2 + 0][0] = r[0]; b0[np * 2 + 0][1] = r[2];
                b0[np * 2 + 1][0] = r[1]; b0[np * 2 + 1][1] = r[3];
            }
            uint32_t a[2][4];
            #pragma unroll
            for (int mf = 0; mf < 2; mf++)
                LDSM4(a[mf], st + aRow[mf] + (((ck ^ aSw[mf])) << 4));
            #pragma unroll
            for (int mf = 0; mf < 2; mf++)
                #pragma unroll
                for (int nf = 0; nf < 4; nf++)
                    MMA_F16(acc[mf][nf], a[mf], b0[nf]);
        }
    }
    #undef ISSUE

    const int er = lane >> 2;
    const int ec = (lane & 3) * 2;
    __half* Hout = z ? H1 : H0;
    #pragma unroll
    for (int mf = 0; mf < 2; mf++) {
        const int row0 = rowBase + warpM * 32 + mf * 16 + er;
        #pragma unroll
        for (int nf = 0; nf < 4; nf++) {
            const int col = colBase + warpN * 32 + nf * 8 + ec;
            const float a0 = acc[mf][nf][0] * WSCALE_INV;
            const float a1 = acc[mf][nf][1] * WSCALE_INV;
            const float a2 = acc[mf][nf][2] * WSCALE_INV;
            const float a3 = acc[mf][nf][3] * WSCALE_INV;
            if (RES) {
                const __half2 r0 = *(const __half2*)(res + (size_t)row0 * DD + col);
                const __half2 r1 = *(const __half2*)(res + (size_t)(row0 + 8) * DD + col);
                float2 v0 = make_float2(a0 + __half2float(r0.x), a1 + __half2float(r0.y));
                float2 v1 = make_float2(a2 + __half2float(r1.x), a3 + __half2float(r1.y));
                *(float2*)(F + (size_t)row0 * DD + col) = v0;
                *(float2*)(F + (size_t)(row0 + 8) * DD + col) = v1;
            } else {
                *(uint32_t*)(Hout + (size_t)row0 * DD + col) = pack_h(a0, a1);
                *(uint32_t*)(Hout + (size_t)(row0 + 8) * DD + col) = pack_h(a2, a3);
            }
        }
    }
}

// ======================= A conversion (fp32 -> fp16) ========================
__global__ __launch_bounds__(256) void tohalf_kernel(
    const float* __restrict__ in0, const float* __restrict__ in1,
    __half* __restrict__ o)
{
    const size_t e = ((size_t)blockIdx.x * 256 + threadIdx.x) * 8;
    const float* in = blockIdx.y ? in1 : in0;
    const size_t oz = (size_t)blockIdx.y * ((size_t)MM * DD);
    float4 v0 = *(const float4*)(in + e);
    float4 v1 = *(const float4*)(in + e + 4);
    uint4 h = make_uint4(pack_h(v0.x, v0.y), pack_h(v0.z, v0.w),
                         pack_h(v1.x, v1.y), pack_h(v1.z, v1.w));
    *(uint4*)(o + oz + e) = h;
}

// ======================= weight transpose (x256, fp16) ======================
__global__ __launch_bounds__(256) void wsplit_kernel(
    const float* __restrict__ W0, const float* __restrict__ W1,
    __half* __restrict__ bh)
{
    __shared__ float tile[32][33];
    const float* W = blockIdx.z ? W1 : W0;
    const size_t oz = (size_t)blockIdx.z * DD * DD;
    const int tx = threadIdx.x & 31, ty0 = threadIdx.x >> 5;
    const int nbase = blockIdx.x * 32, kbase = blockIdx.y * 32;
    #pragma unroll
    for (int j = 0; j < 4; j++) {
        int r = ty0 + j * 8;
        tile[r][tx] = W[(size_t)(kbase + r) * DD + nbase + tx];
    }
    __syncthreads();
    #pragma unroll
    for (int j = 0; j < 4; j++) {
        int n = nbase + ty0 + j * 8;
        int k = kbase + tx;
        bh[oz + (size_t)n * DD + k] = __float2half_rn(tile[tx][ty0 + j * 8] * WSCALE);
    }
}

// ======= per-batch gk-scaled WP transpose: BP[b][n][k] = WP[k][n]*gk[b,k]*256
__global__ __launch_bounds__(256) void wpscale_kernel(
    const float* __restrict__ WP, const float* __restrict__ gk,
    __half* __restrict__ bp)
{
    __shared__ float tile[32][33];
    const int b = blockIdx.z;
    const size_t oz = (size_t)b * DD * DD;
    const int tx = threadIdx.x & 31, ty0 = threadIdx.x >> 5;
    const int nbase = blockIdx.x * 32, kbase = blockIdx.y * 32;
    #pragma unroll
    for (int j = 0; j < 4; j++) {
        int r = ty0 + j * 8;
        tile[r][tx] = WP[(size_t)(kbase + r) * DD + nbase + tx];
    }
    __syncthreads();
    const float gv = gk[b * DD + kbase + tx] * WSCALE;
    #pragma unroll
    for (int j = 0; j < 4; j++) {
        int n = nbase + ty0 + j * 8;
        int k = kbase + tx;
        bp[oz + (size_t)n * DD + k] = __float2half_rn(tile[tx][ty0 + j * 8] * gv);
    }
}

// ======================= small-W transpose (Wq/Wk -> Wt[h][d]) ==============
__global__ __launch_bounds__(256) void wtrans_kernel(
    const float* __restrict__ W0, const float* __restrict__ W1,
    float* __restrict__ Wt)
{
    const int idx = blockIdx.x * 256 + threadIdx.x;      // 0..16383
    const float* W = blockIdx.y ? W1 : W0;
    const int h = idx >> 10, d = idx & (DD - 1);
    Wt[blockIdx.y * (HH * DD) + idx] = W[d * HH + h];
}

// ======================= middle kernels =====================================
// 4 rows per block, float4 dot loop.
// logits[b,h,s] = 0.125 * X[m,:]@Wt[h,:] - (1-mask[m])*1e8   (X fp16)
__global__ __launch_bounds__(256) void logits_kernel(
    const __half* __restrict__ X, const float* __restrict__ Wt,
    const float* __restrict__ mask, float* __restrict__ logits)
{
    const int m0 = blockIdx.x * 4;
    const int b  = m0 >> 11;
    const int s0 = m0 & (SS - 1);
    const int tid = threadIdx.x;

    __shared__ float xs[4][DD];     // 16 KB
    __shared__ float red[4][256];   //  4 KB

    // load 4 rows (4096 halfs): each thread 2x uint4 (8 halfs each)
    #pragma unroll
    for (int t = 0; t < 2; t++) {
        const int idx = tid + t * 256;          // 0..511 units of 8 halfs
        const int r = idx >> 7;                 // row 0..3
        const int c = (idx & 127) * 8;
        const uint4 hv = *(const uint4*)(X + (size_t)(m0 + r) * DD + c);
        const __half2* hp = (const __half2*)&hv;
        float2 f0 = __half22float2(hp[0]);
        float2 f1 = __half22float2(hp[1]);
        float2 f2 = __half22float2(hp[2]);
        float2 f3 = __half22float2(hp[3]);
        float4* dst = (float4*)&xs[r][c];
        dst[0] = make_float4(f0.x, f0.y, f1.x, f1.y);
        dst[1] = make_float4(f2.x, f2.y, f3.x, f3.y);
    }
    __syncthreads();

    const int h = tid >> 4, g = tid & 15;
    const float4* w4 = (const float4*)(Wt + h * DD);
    float a0 = 0.f, a1 = 0.f, a2 = 0.f, a3 = 0.f;
    #pragma unroll
    for (int j = 0; j < 16; j++) {
        const float4 w = w4[g + 16 * j];
        const float4 x0 = ((const float4*)xs[0])[g + 16 * j];
        const float4 x1 = ((const float4*)xs[1])[g + 16 * j];
        const float4 x2 = ((const float4*)xs[2])[g + 16 * j];
        const float4 x3 = ((const float4*)xs[3])[g + 16 * j];
        a0 += x0.x * w.x + x0.y * w.y + x0.z * w.z + x0.w * w.w;
        a1 += x1.x * w.x + x1.y * w.y + x1.z * w.z + x1.w * w.w;
        a2 += x2.x * w.x + x2.y * w.y + x2.z * w.z + x2.w * w.w;
        a3 += x3.x * w.x + x3.y * w.y + x3.z * w.z + x3.w * w.w;
    }
    red[0][tid] = a0; red[1][tid] = a1; red[2][tid] = a2; red[3][tid] = a3;
    __syncthreads();

    if (tid < 64) {
        const int r = tid >> 4, hh = tid & 15;
        float v = 0.f;
        #pragma unroll
        for (int g2 = 0; g2 < 16; g2++) v += red[r][hh * 16 + g2];
        logits[((size_t)(b * HH + hh)) * SS + (s0 + r)] =
            v * 0.125f - (1.f - mask[m0 + r]) * 1e8f;
    }
}

// fused k logits: 4 rows per block; row s' of QK_flat gathered from fp16 K
// scaled by gq.  hp = s'>>7 is invariant within an aligned block of 4.
__global__ __launch_bounds__(256) void k_logits_kernel(
    const __half* __restrict__ K, const float* __restrict__ gq,
    const float* __restrict__ Wt, const float* __restrict__ mask,
    float* __restrict__ logits)
{
    const int m0 = blockIdx.x * 4;
    const int b  = m0 >> 11;
    const int s0 = m0 & (SS - 1);
    const int hp = s0 >> 7;
    const int tid = threadIdx.x;

    __shared__ float xs[4][DD];     // 16 KB
    __shared__ float red[4][256];   //  4 KB

    // gather: 64 (r,j) segments x 64 halfs; thread covers (seg, quarter)
    {
        const int seg = tid >> 2;              // 0..63
        const int q   = tid & 3;               // quarter of 64 halfs
        const int r   = seg >> 4;              // row 0..3
        const int j   = seg & 15;              // K-subrow 0..15
        const int srcRow = ((s0 + r) & 127) * 16 + j;
        const int dh0 = q * 16;
        const float* gqr = gq + (size_t)(b * HH + hp) * DHH + dh0;
        const __half* src = K + ((size_t)(b * SS + srcRow)) * DD + hp * DHH + dh0;
        float* dst = &xs[r][j * 64 + dh0];
        #pragma unroll
        for (int t = 0; t < 2; t++) {
            const uint4 hv = *(const uint4*)(src + t * 8);
            const __half2* hpv = (const __half2*)&hv;
            #pragma unroll
            for (int u = 0; u < 4; u++) {
                const float2 f = __half22float2(hpv[u]);
                dst[t * 8 + 2 * u]     = f.x * gqr[t * 8 + 2 * u];
                dst[t * 8 + 2 * u + 1] = f.y * gqr[t * 8 + 2 * u + 1];
            }
        }
    }
    __syncthreads();

    const int h = tid >> 4, g = tid & 15;
    const float4* w4 = (const float4*)(Wt + h * DD);
    float a0 = 0.f, a1 = 0.f, a2 = 0.f, a3 = 0.f;
    #pragma unroll
    for (int j = 0; j < 16; j++) {
        const float4 w = w4[g + 16 * j];
        const float4 x0 = ((const float4*)xs[0])[g + 16 * j];
        const float4 x1 = ((const float4*)xs[1])[g + 16 * j];
        const float4 x2 = ((const float4*)xs[2])[g + 16 * j];
        const float4 x3 = ((const float4*)xs[3])[g + 16 * j];
        a0 += x0.x * w.x + x0.y * w.y + x0.z * w.z + x0.w * w.w;
        a1 += x1.x * w.x + x1.y * w.y + x1.z * w.z + x1.w * w.w;
        a2 += x2.x * w.x + x2.y * w.y + x2.z * w.z + x2.w * w.w;
        a3 += x3.x * w.x + x3.y * w.y + x3.z * w.z + x3.w * w.w;
    }
    red[0][tid] = a0; red[1][tid] = a1; red[2][tid] = a2; red[3][tid] = a3;
    __syncthreads();

    if (tid < 64) {
        const int r = tid >> 4, hh = tid & 15;
        float v = 0.f;
        #pragma unroll
        for (int g2 = 0; g2 < 16; g2++) v += red[r][hh * 16 + g2];
        logits[((size_t)(b * HH + hh)) * SS + (s0 + r)] =
            v * 0.125f - (1.f - mask[m0 + r]) * 1e8f;
    }
}

// att = softmax(logits[b,h,:]); gout = (gmul?) * sum_s att[s]*src.
// 512 threads; phase 3 warp-per-row (coalesced 128B rows).
template<bool GM>
__global__ __launch_bounds__(512) void softmax_wsum_kernel(
    const float* __restrict__ logits, const __half* __restrict__ src,
    float* __restrict__ gout, const float* __restrict__ gmul)
{
    const int b = blockIdx.x >> 4, h = blockIdx.x & 15;
    const int tid = threadIdx.x;
    const float* lrow = logits + (size_t)(b * HH + h) * SS;

    __shared__ float att[SS];        // 8 KB
    __shared__ float red[1024];      // 4 KB

    float mx = -3.4e38f;
    for (int s = tid; s < SS; s += 512) mx = fmaxf(mx, lrow[s]);
    red[tid] = mx; __syncthreads();
    for (int off = 256; off > 0; off >>= 1) {
        if (tid < off) red[tid] = fmaxf(red[tid], red[tid + off]);
        __syncthreads();
    }
    mx = red[0];
    __syncthreads();

    float sum = 0.f;
    for (int s = tid; s < SS; s += 512) {
        float e = expf(lrow[s] - mx);
        att[s] = e;
        sum += e;
    }
    red[tid] = sum; __syncthreads();
    for (int off = 256; off > 0; off >>= 1) {
        if (tid < off) red[tid] += red[tid + off];
        __syncthreads();
    }
    const float inv = 1.f / red[0];
    __syncthreads();

    const int w = tid >> 5, l = tid & 31;
    const __half* base = src + (size_t)b * (SS * DD) + h * DHH + 2 * l;
    float2 acc = make_float2(0.f, 0.f);
    #pragma unroll 4
    for (int s = w; s < SS; s += 16) {
        const float a = att[s];
        const float2 f = __half22float2(*(const __half2*)(base + (size_t)s * DD));
        acc.x += a * f.x;
        acc.y += a * f.y;
    }
    red[w * 64 + 2 * l]     = acc.x;
    red[w * 64 + 2 * l + 1] = acc.y;
    __syncthreads();

    if (tid < DHH) {
        float v = 0.f;
        #pragma unroll
        for (int jj = 0; jj < 16; jj++) v += red[jj * 64 + tid];
        float r = v * inv;
        if (GM) r *= gmul[(b * HH + h) * DHH + tid];
        gout[(b * HH + h) * DHH + tid] = r;
    }
}

// ===========================================================================
extern "C" void kernel_launch(void* const* d_in, const int* in_sizes, int n_in,
                              void* d_out, int out_size)
{
    const float* Qseq  = (const float*)d_in[0];
    const float* Kseq  = (const float*)d_in[1];
    const float* Qmask = (const float*)d_in[2];
    const float* Kmask = (const float*)d_in[3];
    const float* WQ    = (const float*)d_in[4];
    const float* WK    = (const float*)d_in[5];
    const float* Wq    = (const float*)d_in[6];
    const float* Wk    = (const float*)d_in[7];
    const float* WP    = (const float*)d_in[8];
    float* out = (float*)d_out;

    float *pL, *pgq, *pgk, *pWt;
    __half *pQh, *pKh, *pA, *pB, *pBP;
    cudaGetSymbolAddress((void**)&pQh, g_Qh);
    cudaGetSymbolAddress((void**)&pKh, g_Kh);
    cudaGetSymbolAddress((void**)&pL,  g_logits);
    cudaGetSymbolAddress((void**)&pgq, g_gq);
    cudaGetSymbolAddress((void**)&pgk, g_gk);
    cudaGetSymbolAddress((void**)&pWt, g_Wt);
    cudaGetSymbolAddress((void**)&pA,  g_Af16);
    cudaGetSymbolAddress((void**)&pB,  g_Bf16);
    cudaGetSymbolAddress((void**)&pBP, g_BP);

    cudaFuncSetAttribute(hmma_gemm_kernel<false>,
                         cudaFuncAttributeMaxDynamicSharedMemorySize, GEMM_SMEM);
    cudaFuncSetAttribute(hmma_gemm_kernel<true>,
                         cudaFuncAttributeMaxDynamicSharedMemorySize, GEMM_SMEM);

    const int spB = (MM * DD) / 8 / 256;   // 8192 blocks per input

    // 0) transpose Wq/Wk for the logits kernels
    wtrans_kernel<<<dim3(64, 2), 256>>>(Wq, Wk, pWt);

    // 1+2) Q = Q_seq @ WQ and K = K_seq @ WK  (merged, fp16 outputs)
    tohalf_kernel<<<dim3(spB, 2), 256>>>(Qseq, Kseq, pA);
    wsplit_kernel<<<dim3(32, 32, 2), 256>>>(WQ, WK, pB);
    hmma_gemm_kernel<false><<<dim3(16, 128, 2), 256, GEMM_SMEM>>>(
        pA, pB, pQh, pKh, nullptr, nullptr);

    // 3) q logits + softmax + global_q
    logits_kernel<<<MM / 4, 256>>>(pQh, pWt, Qmask, pL);
    softmax_wsum_kernel<false><<<BB * HH, 512>>>(pL, pQh, pgq, nullptr);

    // 4) k logits (fused QK gather) + softmax + global_k (fused gq mul)
    k_logits_kernel<<<MM / 4, 256>>>(pKh, pgq, pWt + HH * DD, Kmask, pL);
    softmax_wsum_kernel<true><<<BB * HH, 512>>>(pL, pKh, pgk, pgq);

    // 5) out = Q @ (diag(gk_b)·WP) + Q   (gk folded into per-batch B)
    wpscale_kernel<<<dim3(32, 32, 8), 256>>>(WP, pgk, pBP);
    hmma_gemm_kernel<true><<<dim3(16, 128, 1), 256, GEMM_SMEM>>>(
        pQh, pBP, nullptr, nullptr, out, pQh);
}